// round 2
// baseline (speedup 1.0000x reference)
#include <cuda_runtime.h>
#include <cuda_fp16.h>
#include <cstdint>

// ======================= problem constants =======================
#define MDIM 32768      // B*S = 16*2048
#define NDIM 4096       // out features
#define KDIM 1024       // in features
#define SEQ  2048
#define NBATCH 16

#define BM 128
#define BN 128
#define BK 64                 // halves per K-slab = 128 bytes = one SW128 row
#define NKT (KDIM / BK)       // 16
#define STAGES 3

#define TILEB  (BM * BK * 2)        // 16384 bytes per tile
#define STAGEB (2 * TILEB)          // A + B = 32768
#define SMEMB  (STAGES * STAGEB)    // 98304

// ======================= static fp16 scratch (no allocs) =======================
__device__ __align__(1024) __half g_xh[(size_t)MDIM * KDIM];            // 64 MB
__device__ __align__(1024) __half g_wc[(size_t)NBATCH * NDIM * KDIM];   // 128 MB: W - lr_b*G

// ======================= PTX helpers (all plain sm_90-and-below features) =======================
__device__ __forceinline__ uint32_t smem_u32(const void* p) {
    uint32_t a;
    asm("{ .reg .u64 t; cvta.to.shared.u64 t, %1; cvt.u32.u64 %0, t; }" : "=r"(a) : "l"(p));
    return a;
}

#define SW128(o) ((o) ^ (((o) >> 3) & 0x70))

__device__ __forceinline__ void cp_async_16(uint32_t dst, const void* src) {
    asm volatile("cp.async.cg.shared.global [%0], [%1], 16;" :: "r"(dst), "l"(src));
}
__device__ __forceinline__ void cp_commit() {
    asm volatile("cp.async.commit_group;" ::: "memory");
}
template <int N>
__device__ __forceinline__ void cp_wait() {
    asm volatile("cp.async.wait_group %0;" :: "n"(N) : "memory");
}

__device__ __forceinline__ void ldsm4(uint32_t* d, uint32_t addr) {
    asm volatile("ldmatrix.sync.aligned.m8n8.x4.shared.b16 {%0,%1,%2,%3}, [%4];"
                 : "=r"(d[0]), "=r"(d[1]), "=r"(d[2]), "=r"(d[3]) : "r"(addr));
}

__device__ __forceinline__ void mma16816(float* c, const uint32_t* a, uint32_t b0, uint32_t b1) {
    asm volatile(
        "mma.sync.aligned.m16n8k16.row.col.f32.f16.f16.f32 "
        "{%0,%1,%2,%3}, {%4,%5,%6,%7}, {%8,%9}, {%0,%1,%2,%3};"
        : "+f"(c[0]), "+f"(c[1]), "+f"(c[2]), "+f"(c[3])
        : "r"(a[0]), "r"(a[1]), "r"(a[2]), "r"(a[3]), "r"(b0), "r"(b1));
}

// ======================= pre-conversion kernels =======================
__global__ void __launch_bounds__(256) cvt_x_kernel(const float* __restrict__ src) {
    size_t idx = ((size_t)blockIdx.x * 256 + threadIdx.x) * 4;
    float4 v = *reinterpret_cast<const float4*>(src + idx);
    *reinterpret_cast<__half2*>(g_xh + idx)     = __floats2half2_rn(v.x, v.y);
    *reinterpret_cast<__half2*>(g_xh + idx + 2) = __floats2half2_rn(v.z, v.w);
}

// Wc[b] = W - lr_b * G  (fp16). One read of W/G serves all 16 batches.
__global__ void __launch_bounds__(256) build_wc_kernel(const float* __restrict__ w,
                                                       const float* __restrict__ g,
                                                       const float* __restrict__ lr) {
    size_t idx = ((size_t)blockIdx.x * 256 + threadIdx.x) * 4;
    float4 vw = *reinterpret_cast<const float4*>(w + idx);
    float4 vg = *reinterpret_cast<const float4*>(g + idx);
    #pragma unroll
    for (int b = 0; b < NBATCH; ++b) {
        float l = __ldg(lr + b);
        __half2 h0 = __floats2half2_rn(vw.x - l * vg.x, vw.y - l * vg.y);
        __half2 h1 = __floats2half2_rn(vw.z - l * vg.z, vw.w - l * vg.w);
        __half* dst = g_wc + (size_t)b * NDIM * KDIM + idx;
        *reinterpret_cast<__half2*>(dst)     = h0;
        *reinterpret_cast<__half2*>(dst + 2) = h1;
    }
}

// ======================= GEMM kernel =======================
// out[m, n] = sum_k xh[m,k] * wc[b(m), n, k] + bias[n] - lr_b*gb[n]
// 128 threads = 4 warps in a 2x2 grid, warp tile 64x64, mma m16n8k16.
__device__ __forceinline__ void load_stage(uint32_t stage_base, const __half* Ag,
                                           const __half* Bg, int kt, int tid) {
    const int k0 = kt * BK;
    #pragma unroll
    for (int i = 0; i < 8; ++i) {           // A tile: 1024 x 16B chunks
        int c = tid + i * 128;
        int r = c >> 3, ch = c & 7;
        cp_async_16(stage_base + SW128(r * 128 + ch * 16), Ag + (size_t)r * KDIM + k0 + ch * 8);
    }
    #pragma unroll
    for (int i = 0; i < 8; ++i) {           // B tile
        int c = tid + i * 128;
        int r = c >> 3, ch = c & 7;
        cp_async_16(stage_base + TILEB + SW128(r * 128 + ch * 16), Bg + (size_t)r * KDIM + k0 + ch * 8);
    }
}

__global__ void __launch_bounds__(128, 2) gemm_kernel(const float* __restrict__ bias,
                                                      const float* __restrict__ gbias,
                                                      const float* __restrict__ lr_arr,
                                                      float* __restrict__ out) {
    extern __shared__ char smem[];
    const uint32_t sb = smem_u32(smem);
    const int tid  = threadIdx.x;
    const int warp = tid >> 5, lane = tid & 31;
    const int warp_m = (warp & 1) * 64;
    const int warp_n = (warp >> 1) * 64;

    const int rowA0 = blockIdx.y * BM;
    const int colB0 = blockIdx.x * BN;
    const int batch = blockIdx.y >> 4;     // BM*16 == SEQ

    const __half* Ag = g_xh + (size_t)rowA0 * KDIM;
    const __half* Bg = g_wc + ((size_t)batch * NDIM + colB0) * KDIM;

    float acc[4][8][4];
    #pragma unroll
    for (int i = 0; i < 4; ++i)
        #pragma unroll
        for (int j = 0; j < 8; ++j)
            #pragma unroll
            for (int t = 0; t < 4; ++t) acc[i][j][t] = 0.0f;

    // prologue: prefetch STAGES-1 tiles
    #pragma unroll
    for (int p = 0; p < STAGES - 1; ++p) {
        load_stage(sb + p * STAGEB, Ag, Bg, p, tid);
        cp_commit();
    }

    for (int kt = 0; kt < NKT; ++kt) {
        cp_wait<STAGES - 2>();
        __syncthreads();

        const int nxt = kt + STAGES - 1;
        if (nxt < NKT) {
            load_stage(sb + (nxt % STAGES) * STAGEB, Ag, Bg, nxt, tid);
            cp_commit();
        }

        const uint32_t Ab = sb + (kt % STAGES) * STAGEB;
        const uint32_t Bb = Ab + TILEB;

        #pragma unroll
        for (int ks = 0; ks < 4; ++ks) {
            // A fragments: 4 x m16k16
            uint32_t afr[4][4];
            #pragma unroll
            for (int mf = 0; mf < 4; ++mf) {
                int row = warp_m + mf * 16 + (lane & 15);
                int col = ks * 16 + (lane >> 4) * 8;
                ldsm4(afr[mf], Ab + SW128(row * 128 + col * 2));
            }
            // B fragments: 4 x (two n8k16 frags each)
            uint32_t bfr[4][4];
            #pragma unroll
            for (int np = 0; np < 4; ++np) {
                int row = warp_n + np * 16 + ((lane >> 4) * 8 + (lane & 7));
                int col = ks * 16 + ((lane >> 3) & 1) * 8;
                ldsm4(bfr[np], Bb + SW128(row * 128 + col * 2));
            }
            #pragma unroll
            for (int mf = 0; mf < 4; ++mf) {
                #pragma unroll
                for (int np = 0; np < 4; ++np) {
                    mma16816(acc[mf][2 * np],     afr[mf], bfr[np][0], bfr[np][1]);
                    mma16816(acc[mf][2 * np + 1], afr[mf], bfr[np][2], bfr[np][3]);
                }
            }
        }
    }

    // ---------- epilogue ----------
    __syncthreads();
    float* bias_s = reinterpret_cast<float*>(smem);
    float* gb_s   = bias_s + BN;
    bias_s[tid] = bias[colB0 + tid];        // 128 threads == BN
    gb_s[tid]   = gbias[colB0 + tid];
    __syncthreads();

    const float lr = __ldg(lr_arr + batch);

    #pragma unroll
    for (int mf = 0; mf < 4; ++mf) {
        const int gr0 = rowA0 + warp_m + mf * 16 + (lane >> 2);
        #pragma unroll
        for (int nf = 0; nf < 8; ++nf) {
            const int cl = warp_n + nf * 8 + (lane & 3) * 2;
            const float bc0 = bias_s[cl]     - lr * gb_s[cl];
            const float bc1 = bias_s[cl + 1] - lr * gb_s[cl + 1];
            float2 v0 = make_float2(acc[mf][nf][0] + bc0, acc[mf][nf][1] + bc1);
            float2 v1 = make_float2(acc[mf][nf][2] + bc0, acc[mf][nf][3] + bc1);
            *reinterpret_cast<float2*>(out + (size_t)gr0 * NDIM + colB0 + cl)       = v0;
            *reinterpret_cast<float2*>(out + (size_t)(gr0 + 8) * NDIM + colB0 + cl) = v1;
        }
    }
}

// ======================= launch =======================
extern "C" void kernel_launch(void* const* d_in, const int* in_sizes, int n_in,
                              void* d_out, int out_size) {
    (void)in_sizes; (void)n_in; (void)out_size;
    const float* x    = (const float*)d_in[0];
    const float* w    = (const float*)d_in[1];
    const float* bias = (const float*)d_in[2];
    const float* g    = (const float*)d_in[3];
    const float* gb   = (const float*)d_in[4];
    const float* lr   = (const float*)d_in[5];
    float* out = (float*)d_out;

    static bool attr_set = false;
    if (!attr_set) {
        cudaFuncSetAttribute(gemm_kernel, cudaFuncAttributeMaxDynamicSharedMemorySize, SMEMB);
        attr_set = true;
    }

    cvt_x_kernel<<<(size_t)MDIM * KDIM / 4 / 256, 256>>>(x);
    build_wc_kernel<<<(size_t)NDIM * KDIM / 4 / 256, 256>>>(w, g, lr);

    dim3 grid(NDIM / BN, MDIM / BM);   // (32, 256): N fastest for A-tile L2 reuse
    gemm_kernel<<<grid, 128, SMEMB>>>(bias, gb, lr, out);
}